// round 13
// baseline (speedup 1.0000x reference)
#include <cuda_runtime.h>
#include <cuda_fp16.h>
#include <cstdint>

// ---------------------------------------------------------------------------
// softplus( exp(-0.5*||x_i - c_j||^2) @ beta ),  N=40000, M=4000, D=32.
//
// R11 (re-run; prior round was an infra failure, not a kernel result):
// f16-input / f32-accum MMA; exp split across pipes to break the MUFU floor
// (R10 measurement: wall == MUFU-saturation time exactly).
//   seed d0..d3 = (G_{c0}, G_{c1}, G_{c0}, G_{c1})       [MOVs, no FADD]
//   d = dot*log2e + G                                     [f32, mma C-op]
//   3 of 4 exps: MUFU ex2.approx.f32
//   1 of 4 exps: fma-pipe exp2 poly (magic-add range reduction, deg-3,
//                bit-trick 2^k scale -> p_bits + (y_bits<<23))
//   row = ex2(bx_i) * sum  (bx applied once per row; args stay f32-safe)
// Structure (576 thr, 6 row-groups x 3 center-thirds, NB=192, cp.async.bulk
// double buffering, in-kernel A image) unchanged from R10.
// ---------------------------------------------------------------------------

#define LOG2E 1.4426950408889634f

constexpr int D     = 32;
constexpr int RC    = 96;        // rows per CTA
constexpr int NB    = 192;       // centers per tile
constexpr int MAXCT = 43;        // max center tiles (M <= 8256)
constexpr int MAXM  = MAXCT * NB;
constexpr int ROWB  = 64;        // bytes per f16 image row (32 f16)
constexpr int GPT   = NB / 2;    // G pairs per tile = 96

__device__ __align__(128) uint8_t g_cI[(size_t)MAXM * ROWB];  // f16(c*log2e), swizzled
__device__ float2 g_G2[MAXCT * GPT];  // (G_{2p}, G_{2p+1}), permuted per-tile layout

// pack two f32 into f16x2: lo -> bits[0:16], hi -> bits[16:32]
__device__ __forceinline__ uint32_t pack_hf2(float lo, float hi) {
    uint32_t h;
    asm("cvt.rn.f16x2.f32 %0, %1, %2;" : "=r"(h) : "f"(hi), "f"(lo));
    return h;
}

__device__ __forceinline__ float ex2f(float x) {
    float r;
    asm("ex2.approx.ftz.f32 %0, %1;" : "=f"(r) : "f"(x));
    return r;
}

// exp2 on the fma pipe: magic-add range reduction + deg-3 poly + bit scale.
// Valid for v in [-80, 60]; clamps below -80 (contributions ~2^-80 ~ 0).
__device__ __forceinline__ float exp2_poly(float v) {
    v = fmaxf(v, -80.0f);
    float y = v + 12582912.0f;            // RN -> k integer in mantissa
    float z = y - 12582912.0f;            // z = rni(v)
    float f = v - z;                      // f in [-0.5, 0.5]
    float p = fmaf(f, 0.0576060f, 0.2402265f);
    p = fmaf(f, p, 0.6931472f);
    p = fmaf(f, p, 1.0f);
    // 2^k scale: y_bits = 0x4B400000 + k, and (0x4B400000 << 23) == 0 mod 2^32
    uint32_t r = __float_as_uint(p) + (__float_as_uint(y) << 23);
    return __uint_as_float(r);
}

// ---- async copy / mbarrier -------------------------------------------------
__device__ __forceinline__ void mbar_init(uint32_t mb, int count) {
    asm volatile("mbarrier.init.shared.b64 [%0], %1;" :: "r"(mb), "r"(count) : "memory");
}
__device__ __forceinline__ void mbar_expect_tx(uint32_t mb, uint32_t bytes) {
    asm volatile("mbarrier.arrive.expect_tx.shared.b64 _, [%0], %1;"
                 :: "r"(mb), "r"(bytes) : "memory");
}
__device__ __forceinline__ void bulk_g2s(uint32_t sdst, const void* gsrc,
                                         uint32_t bytes, uint32_t mb) {
    asm volatile(
        "cp.async.bulk.shared::cta.global.mbarrier::complete_tx::bytes "
        "[%0], [%1], %2, [%3];"
        :: "r"(sdst), "l"(gsrc), "r"(bytes), "r"(mb) : "memory");
}
__device__ __forceinline__ void mbar_wait(uint32_t mb, uint32_t parity) {
    uint32_t done;
    asm volatile(
        "{\n\t.reg .pred p;\n\t"
        "mbarrier.try_wait.parity.acquire.cta.shared::cta.b64 p, [%1], %2;\n\t"
        "selp.b32 %0, 1, 0, p;\n\t}"
        : "=r"(done) : "r"(mb), "r"(parity) : "memory");
    if (!done) {
        asm volatile(
            "{\n\t.reg .pred P1;\n\t"
            "WL_%=:\n\t"
            "mbarrier.try_wait.parity.acquire.cta.shared::cta.b64 P1, [%0], %1, 0x989680;\n\t"
            "@P1 bra.uni WD_%=;\n\t"
            "bra.uni WL_%=;\n\t"
            "WD_%=:\n\t}"
            :: "r"(mb), "r"(parity) : "memory");
    }
}

// ---- warp MMA primitives ---------------------------------------------------
__device__ __forceinline__ void ldmx4(uint32_t& r0, uint32_t& r1,
                                      uint32_t& r2, uint32_t& r3, uint32_t addr) {
    asm volatile("ldmatrix.sync.aligned.m8n8.x4.shared.b16 {%0,%1,%2,%3}, [%4];"
                 : "=r"(r0), "=r"(r1), "=r"(r2), "=r"(r3) : "r"(addr));
}

__device__ __forceinline__ void mma16816f(float& d0, float& d1, float& d2, float& d3,
                                          uint32_t a0, uint32_t a1, uint32_t a2, uint32_t a3,
                                          uint32_t b0, uint32_t b1) {
    asm volatile(
        "mma.sync.aligned.m16n8k16.row.col.f32.f16.f16.f32 "
        "{%0,%1,%2,%3}, {%4,%5,%6,%7}, {%8,%9}, {%0,%1,%2,%3};"
        : "+f"(d0), "+f"(d1), "+f"(d2), "+f"(d3)
        : "r"(a0), "r"(a1), "r"(a2), "r"(a3), "r"(b0), "r"(b1));
}

// ---------------------------------------------------------------------------
// prep_c: one thread per HALF center row. Writes the 64B f16 image row
// (c*log2e, chunk swizzle phys = logical ^ ((j>>1)&3)) and, for pair leaders,
// the float2 G pair in the permuted layout [tile][colpair 0..3][group 0..23].
// G = -0.5||c||^2*log2e + log2(beta); padded rows: zero image, G = -1e30.
// ---------------------------------------------------------------------------
__global__ void prep_c(const float* __restrict__ c,
                       const float* __restrict__ beta, int M, int mpad) {
    int idx  = blockIdx.x * blockDim.x + threadIdx.x;
    int j    = idx >> 1;
    int half = idx & 1;
    int lane = idx & 31;
    if (j >= mpad) return;

    float v[16];
    if (j < M) {
        const float4* cp = reinterpret_cast<const float4*>(c + (size_t)j * D + half * 16);
        #pragma unroll
        for (int q = 0; q < 4; q++) {
            float4 t = cp[q];
            v[4 * q] = t.x; v[4 * q + 1] = t.y; v[4 * q + 2] = t.z; v[4 * q + 3] = t.w;
        }
    } else {
        #pragma unroll
        for (int k = 0; k < 16; k++) v[k] = 0.f;
    }
    float s = 0.f;
    #pragma unroll
    for (int k = 0; k < 16; k++) {
        s = fmaf(v[k], v[k], s);
        v[k] *= LOG2E;
    }
    s += __shfl_xor_sync(0xffffffffu, s, 1);   // full ||c||^2

    uint32_t wd[8];
    #pragma unroll
    for (int k = 0; k < 8; k++) wd[k] = pack_hf2(v[2 * k], v[2 * k + 1]);

    const uint32_t key = ((uint32_t)j >> 1) & 3;
    uint8_t* base = g_cI + (size_t)j * ROWB;
    #pragma unroll
    for (int cch = 0; cch < 2; cch++) {
        uint32_t lch = (uint32_t)half * 2 + cch;
        uint4 u = make_uint4(wd[4 * cch], wd[4 * cch + 1], wd[4 * cch + 2], wd[4 * cch + 3]);
        *reinterpret_cast<uint4*>(base + ((lch ^ key) << 4)) = u;
    }

    float Gval = (j < M) ? fmaf(-0.5f * LOG2E, s, log2f(beta[j])) : -1e30f;
    float Gnext = __shfl_down_sync(0xffffffffu, Gval, 2);   // G(j+1)
    if ((lane & 3) == 0) {      // j even, half 0
        int p  = j >> 1;        // global pair index
        int T  = p / GPT;
        int pi = p - T * GPT;   // 0..95
        g_G2[T * GPT + (pi & 3) * 24 + (pi >> 2)] = make_float2(Gval, Gnext);
    }
}

// ---------------------------------------------------------------------------
// Main fused kernel: grid = ceil(N/96), 576 threads (18 warps).
// Warp w: row group wp = w/3 (16 rows), third = w%3 (64 centers of the tile).
// ---------------------------------------------------------------------------
constexpr int SA   = 0;
constexpr int SB0  = 6144;
constexpr int SB1  = 18432;
constexpr int SG0  = 30720;      // float2[96] = 768B
constexpr int SG1  = 31488;
constexpr int SBX  = 32256;      // float[96]
constexpr int SRED = 32640;      // float[3][96]
constexpr int SMB  = 33792;      // mbF0 @+0, mbF1 @+8
constexpr int STOT = 33808;

__global__ void __launch_bounds__(576, 3)
krr_main(const float* __restrict__ x, float* __restrict__ out, int N, int ntiles)
{
    __shared__ __align__(128) uint8_t smem[STOT];
    const uint32_t sbase = (uint32_t)__cvta_generic_to_shared(smem);

    const int tid   = threadIdx.x;
    const int w     = tid >> 5;
    const int lane  = tid & 31;
    const int wp    = w / 3;        // row group 0..5
    const int third = w - wp * 3;   // center third 0..2

    const uint32_t mbF[2] = {sbase + SMB, sbase + SMB + 8};

    if (tid == 0) {
        mbar_init(mbF[0], 1);
        mbar_init(mbF[1], 1);
    }
    asm volatile("fence.proxy.async.shared::cta;" ::: "memory");
    __syncthreads();

    if (tid == 0) {
        mbar_expect_tx(mbF[0], NB * ROWB + GPT * 8);
        bulk_g2s(sbase + SB0, g_cI, NB * ROWB, mbF[0]);
        bulk_g2s(sbase + SG0, g_G2, GPT * 8, mbF[0]);
        if (ntiles > 1) {
            mbar_expect_tx(mbF[1], NB * ROWB + GPT * 8);
            bulk_g2s(sbase + SB1, g_cI + (size_t)NB * ROWB, NB * ROWB, mbF[1]);
            bulk_g2s(sbase + SG1, g_G2 + GPT, GPT * 8, mbF[1]);
        }
    }

    // ---- convert this CTA's 96 x-rows into the swizzled f16 A image -------
    if (tid < 192) {
        int r  = tid >> 1;
        int hh = tid & 1;
        int gr = blockIdx.x * RC + r;
        if (gr > N - 1) gr = N - 1;

        float v[16];
        const float4* xp = reinterpret_cast<const float4*>(x + (size_t)gr * D + hh * 16);
        #pragma unroll
        for (int q = 0; q < 4; q++) {
            float4 t = xp[q];
            v[4 * q] = t.x; v[4 * q + 1] = t.y; v[4 * q + 2] = t.z; v[4 * q + 3] = t.w;
        }
        float s = 0.f;
        #pragma unroll
        for (int k = 0; k < 16; k++) s = fmaf(v[k], v[k], s);
        s += __shfl_xor_sync(0xffffffffu, s, 1);

        uint32_t wd[8];
        #pragma unroll
        for (int k = 0; k < 8; k++) wd[k] = pack_hf2(v[2 * k], v[2 * k + 1]);

        const uint32_t key = ((uint32_t)r >> 1) & 3;
        uint8_t* abase = smem + SA + r * ROWB;
        #pragma unroll
        for (int cch = 0; cch < 2; cch++) {
            uint32_t lch = (uint32_t)hh * 2 + cch;
            uint4 u = make_uint4(wd[4 * cch], wd[4 * cch + 1], wd[4 * cch + 2], wd[4 * cch + 3]);
            *reinterpret_cast<uint4*>(abase + ((lch ^ key) << 4)) = u;
        }
        if (hh == 0)
            *reinterpret_cast<float*>(smem + SBX + r * 4) = -0.5f * s * LOG2E;
    }
    __syncthreads();

    // ---- A fragments (once per warp) ----
    const uint32_t arow = (uint32_t)wp * 16 + (lane & 15);
    const uint32_t akey = (arow >> 1) & 3;
    uint32_t a[8];
    {
        uint32_t ad0 = sbase + SA + arow * ROWB + ((((uint32_t)(lane >> 4) + 0) ^ akey) << 4);
        uint32_t ad1 = sbase + SA + arow * ROWB + ((((uint32_t)(lane >> 4) + 2) ^ akey) << 4);
        ldmx4(a[0], a[1], a[2], a[3], ad0);   // k 0-15
        ldmx4(a[4], a[5], a[6], a[7], ad1);   // k 16-31
    }

    // per-lane B address constant: row = lane&7, chunk = lane>>3 (swizzled)
    const uint32_t l7 = lane & 7;
    const uint32_t boff = l7 * ROWB + ((((uint32_t)lane >> 3) ^ ((l7 >> 1) & 3)) << 4)
                        + (uint32_t)third * 8 * 512;      // this third's groups
    const uint32_t goff = ((uint32_t)(lane & 3) * 24 + (uint32_t)third * 8) * 8;

    float rs_lo = 0.f, rs_hi = 0.f;

    for (int t = 0; t < ntiles; t++) {
        const int buf = t & 1;
        mbar_wait(mbF[buf], (t >> 1) & 1);

        const uint32_t bB = sbase + (buf ? SB1 : SB0) + boff;
        const float2* gBp = reinterpret_cast<const float2*>(smem + (buf ? SG1 : SG0) + goff);

        #pragma unroll
        for (int gg = 0; gg < 8; gg++) {
            uint32_t b0, b1, b2, b3;
            ldmx4(b0, b1, b2, b3, bB + gg * 512);

            float2 Gp = gBp[gg];
            float d0 = Gp.x, d1 = Gp.y, d2 = Gp.x, d3 = Gp.y;
            mma16816f(d0, d1, d2, d3, a[0], a[1], a[2], a[3], b0, b1);
            mma16816f(d0, d1, d2, d3, a[4], a[5], a[6], a[7], b2, b3);

            // 3 exps on MUFU, 1 on the fma pipe
            rs_lo += ex2f(d0) + ex2f(d1);
            rs_hi += ex2f(d2) + exp2_poly(d3);
        }

        __syncthreads();
        if (tid == 0 && t + 2 < ntiles) {
            mbar_expect_tx(mbF[buf], NB * ROWB + GPT * 8);
            bulk_g2s(sbase + (buf ? SB1 : SB0),
                     g_cI + (size_t)(t + 2) * NB * ROWB, NB * ROWB, mbF[buf]);
            bulk_g2s(sbase + (buf ? SG1 : SG0),
                     g_G2 + (size_t)(t + 2) * GPT, GPT * 8, mbF[buf]);
        }
    }

    // ---- reduce across the 4 column-lanes, deposit per-third partials ----
    rs_lo += __shfl_xor_sync(0xffffffffu, rs_lo, 1);
    rs_lo += __shfl_xor_sync(0xffffffffu, rs_lo, 2);
    rs_hi += __shfl_xor_sync(0xffffffffu, rs_hi, 1);
    rs_hi += __shfl_xor_sync(0xffffffffu, rs_hi, 2);

    float* red = reinterpret_cast<float*>(smem + SRED);
    const int lrow = wp * 16 + (lane >> 2);
    if ((lane & 3) == 0) red[third * 96 + lrow]     = rs_lo;
    if ((lane & 3) == 1) red[third * 96 + lrow + 8] = rs_hi;
    __syncthreads();

    // ---- combine thirds, apply 2^bx row factor, softplus, write ----
    if (tid < RC) {
        int r = blockIdx.x * RC + tid;
        if (r < N) {
            const float* bxp = reinterpret_cast<const float*>(smem + SBX);
            float s = ex2f(bxp[tid]) * (red[tid] + red[96 + tid] + red[192 + tid]);
            out[r] = s + log1pf(expf(-s));
        }
    }
}

// ---------------------------------------------------------------------------
extern "C" void kernel_launch(void* const* d_in, const int* in_sizes, int n_in,
                              void* d_out, int out_size) {
    const float* x    = (const float*)d_in[0];  // (N, 32)
    const float* c    = (const float*)d_in[1];  // (M, 32)
    const float* beta = (const float*)d_in[2];  // (M,)
    float* out = (float*)d_out;                 // (N,)

    const int M = in_sizes[2];
    const int N = out_size;

    int nct = (M + NB - 1) / NB;
    if (nct > MAXCT) nct = MAXCT;
    const int mpad = nct * NB;

    prep_c<<<(mpad * 2 + 255) / 256, 256>>>(c, beta, M, mpad);

    const int grid = (N + RC - 1) / RC;
    krr_main<<<grid, 576>>>(x, out, N, nct);
}

// round 14
// speedup vs baseline: 1.1390x; 1.1390x over previous
#include <cuda_runtime.h>
#include <cuda_fp16.h>
#include <cstdint>

// ---------------------------------------------------------------------------
// softplus( exp(-0.5*||x_i - c_j||^2) @ beta ),  N=40000, M=4000, D=32.
//
// R14: R10 (best, MUFU-saturated) + packed f16x2 exp2 offloaded to the fma
// pipe for 6 of 8 groups' d23 pair (f = 0.375 of all exps):
//   poly path (per f16x2 pair, 8 HFMA2-class + 2 ALU ops):
//     v = max(v, -15)                      -- clamped terms -> exact 0
//     y = v + 1536  (f16 RN-to-int)        -- k = y - 1536 in [-15, 11]
//     f = v - (y - 1536)  in [-0.5, 0.5]
//     p = deg-2 Horner(f)                  -- ~0.3% (term errors ~2% already)
//     s_bits = (y_bits - 0x65F165F1) << 10 -- per-lane 2^k, exact (k+15 < 32)
//     result = p * s
//   MUFU path unchanged: ex2.approx.f16x2 (measured rt16 -> no thruput gain,
//   so MUFU keeps only 10 of 16 pairs).
// Everything else (576 thr, 6 row-groups x 3 center-thirds, NB=192, f16-accum
// MMA with G+bx+10 seeds, cp.async.bulk double buffering, in-kernel A image)
// is exactly R10.
// ---------------------------------------------------------------------------

#define LOG2E 1.4426950408889634f

constexpr int D     = 32;
constexpr int RC    = 96;        // rows per CTA
constexpr int NB    = 192;       // centers per tile
constexpr int MAXCT = 43;        // max center tiles (M <= 8256)
constexpr int MAXM  = MAXCT * NB;
constexpr int ROWB  = 64;        // bytes per f16 image row (32 f16)
constexpr int GPT   = NB / 2;    // G pairs per tile = 96

__device__ __align__(128) uint8_t g_cI[(size_t)MAXM * ROWB];  // f16(c*log2e), swizzled
__device__ uint32_t g_G2[MAXCT * GPT];  // f16x2 (G'_{2p}, G'_{2p+1}), permuted layout

// pack two f32 into f16x2: lo -> bits[0:16], hi -> bits[16:32]
__device__ __forceinline__ uint32_t pack_hf2(float lo, float hi) {
    uint32_t h;
    asm("cvt.rn.f16x2.f32 %0, %1, %2;" : "=r"(h) : "f"(hi), "f"(lo));
    return h;
}

// ---- packed f16 math -------------------------------------------------------
__device__ __forceinline__ uint32_t ex2_h2(uint32_t h) {
    uint32_t r;
    asm("ex2.approx.f16x2 %0, %1;" : "=r"(r) : "r"(h));
    return r;
}
__device__ __forceinline__ uint32_t hadd2(uint32_t a, uint32_t b) {
    uint32_t r;
    asm("add.rn.f16x2 %0, %1, %2;" : "=r"(r) : "r"(a), "r"(b));
    return r;
}
__device__ __forceinline__ uint32_t hsub2(uint32_t a, uint32_t b) {
    uint32_t r;
    asm("sub.rn.f16x2 %0, %1, %2;" : "=r"(r) : "r"(a), "r"(b));
    return r;
}
__device__ __forceinline__ uint32_t hmul2(uint32_t a, uint32_t b) {
    uint32_t r;
    asm("mul.rn.f16x2 %0, %1, %2;" : "=r"(r) : "r"(a), "r"(b));
    return r;
}
__device__ __forceinline__ uint32_t hfma2(uint32_t a, uint32_t b, uint32_t c) {
    uint32_t r;
    asm("fma.rn.f16x2 %0, %1, %2, %3;" : "=r"(r) : "r"(a), "r"(b), "r"(c));
    return r;
}
__device__ __forceinline__ uint32_t hmax2(uint32_t a, uint32_t b) {
    uint32_t r;
    asm("max.f16x2 %0, %1, %2;" : "=r"(r) : "r"(a), "r"(b));
    return r;
}
__device__ __forceinline__ float hsum2f(uint32_t h) {
    __half2 v = *reinterpret_cast<__half2*>(&h);
    float2 f = __half22float2(v);
    return f.x + f.y;
}

// packed exp2 on the fma pipe (see header comment).  f16 constants:
//  -15 = 0xCB80, 1536 = 0x6600, -1536 = 0xE600
//  c2 = 0.24023 -> 0x33B0, c1 = 0.70355 -> 0x39A1, c0 = 0.99902 -> 0x3BFE
__device__ __forceinline__ uint32_t exp2h2_poly(uint32_t v) {
    v = hmax2(v, 0xCB80CB80u);            // clamp at -15 (=> s = 0 exactly)
    uint32_t y = hadd2(v, 0x66006600u);   // RN to int via magic 1536
    uint32_t z = hadd2(y, 0xE600E600u);   // z = k (exact)
    uint32_t f = hsub2(v, z);             // f in [-0.5, 0.5]
    uint32_t p = hfma2(f, 0x33B033B0u, 0x39A139A1u);
    p = hfma2(f, p, 0x3BFE3BFEu);
    uint32_t s = (y - 0x65F165F1u) << 10; // per-lane 2^k bits (k+15 in [0,26])
    return hmul2(p, s);
}

// ---- async copy / mbarrier -------------------------------------------------
__device__ __forceinline__ void mbar_init(uint32_t mb, int count) {
    asm volatile("mbarrier.init.shared.b64 [%0], %1;" :: "r"(mb), "r"(count) : "memory");
}
__device__ __forceinline__ void mbar_expect_tx(uint32_t mb, uint32_t bytes) {
    asm volatile("mbarrier.arrive.expect_tx.shared.b64 _, [%0], %1;"
                 :: "r"(mb), "r"(bytes) : "memory");
}
__device__ __forceinline__ void bulk_g2s(uint32_t sdst, const void* gsrc,
                                         uint32_t bytes, uint32_t mb) {
    asm volatile(
        "cp.async.bulk.shared::cta.global.mbarrier::complete_tx::bytes "
        "[%0], [%1], %2, [%3];"
        :: "r"(sdst), "l"(gsrc), "r"(bytes), "r"(mb) : "memory");
}
__device__ __forceinline__ void mbar_wait(uint32_t mb, uint32_t parity) {
    uint32_t done;
    asm volatile(
        "{\n\t.reg .pred p;\n\t"
        "mbarrier.try_wait.parity.acquire.cta.shared::cta.b64 p, [%1], %2;\n\t"
        "selp.b32 %0, 1, 0, p;\n\t}"
        : "=r"(done) : "r"(mb), "r"(parity) : "memory");
    if (!done) {
        asm volatile(
            "{\n\t.reg .pred P1;\n\t"
            "WL_%=:\n\t"
            "mbarrier.try_wait.parity.acquire.cta.shared::cta.b64 P1, [%0], %1, 0x989680;\n\t"
            "@P1 bra.uni WD_%=;\n\t"
            "bra.uni WL_%=;\n\t"
            "WD_%=:\n\t}"
            :: "r"(mb), "r"(parity) : "memory");
    }
}

// ---- warp MMA primitives ---------------------------------------------------
__device__ __forceinline__ void ldmx4(uint32_t& r0, uint32_t& r1,
                                      uint32_t& r2, uint32_t& r3, uint32_t addr) {
    asm volatile("ldmatrix.sync.aligned.m8n8.x4.shared.b16 {%0,%1,%2,%3}, [%4];"
                 : "=r"(r0), "=r"(r1), "=r"(r2), "=r"(r3) : "r"(addr));
}

__device__ __forceinline__ void mma16816h(uint32_t& d01, uint32_t& d23,
                                          uint32_t a0, uint32_t a1, uint32_t a2, uint32_t a3,
                                          uint32_t b0, uint32_t b1) {
    asm volatile(
        "mma.sync.aligned.m16n8k16.row.col.f16.f16.f16.f16 "
        "{%0,%1}, {%2,%3,%4,%5}, {%6,%7}, {%0,%1};"
        : "+r"(d01), "+r"(d23)
        : "r"(a0), "r"(a1), "r"(a2), "r"(a3), "r"(b0), "r"(b1));
}

// ---------------------------------------------------------------------------
// prep_c: one thread per HALF center row. Writes the 64B f16 image row
// (c*log2e, chunk swizzle phys = logical ^ ((j>>1)&3)) and, for pair leaders,
// G' pair f16x2 in the permuted layout [tile][colpair 0..3][group 0..23].
// G' = -0.5||c||^2*log2e + log2(beta) + 10; padded rows: zero image, G' = -30000.
// ---------------------------------------------------------------------------
__global__ void prep_c(const float* __restrict__ c,
                       const float* __restrict__ beta, int M, int mpad) {
    int idx  = blockIdx.x * blockDim.x + threadIdx.x;
    int j    = idx >> 1;
    int half = idx & 1;
    int lane = idx & 31;
    if (j >= mpad) return;

    float v[16];
    if (j < M) {
        const float4* cp = reinterpret_cast<const float4*>(c + (size_t)j * D + half * 16);
        #pragma unroll
        for (int q = 0; q < 4; q++) {
            float4 t = cp[q];
            v[4 * q] = t.x; v[4 * q + 1] = t.y; v[4 * q + 2] = t.z; v[4 * q + 3] = t.w;
        }
    } else {
        #pragma unroll
        for (int k = 0; k < 16; k++) v[k] = 0.f;
    }
    float s = 0.f;
    #pragma unroll
    for (int k = 0; k < 16; k++) {
        s = fmaf(v[k], v[k], s);
        v[k] *= LOG2E;
    }
    s += __shfl_xor_sync(0xffffffffu, s, 1);   // full ||c||^2

    uint32_t wd[8];
    #pragma unroll
    for (int k = 0; k < 8; k++) wd[k] = pack_hf2(v[2 * k], v[2 * k + 1]);

    const uint32_t key = ((uint32_t)j >> 1) & 3;
    uint8_t* base = g_cI + (size_t)j * ROWB;
    #pragma unroll
    for (int cch = 0; cch < 2; cch++) {
        uint32_t lch = (uint32_t)half * 2 + cch;
        uint4 u = make_uint4(wd[4 * cch], wd[4 * cch + 1], wd[4 * cch + 2], wd[4 * cch + 3]);
        *reinterpret_cast<uint4*>(base + ((lch ^ key) << 4)) = u;
    }

    float Gval = (j < M) ? (fmaf(-0.5f * LOG2E, s, log2f(beta[j])) + 10.0f)
                         : -30000.0f;
    float Gnext = __shfl_down_sync(0xffffffffu, Gval, 2);   // G'(j+1)
    if ((lane & 3) == 0) {      // j even, half 0
        int p  = j >> 1;        // global pair index
        int T  = p / GPT;
        int pi = p - T * GPT;   // 0..95
        g_G2[T * GPT + (pi & 3) * 24 + (pi >> 2)] = pack_hf2(Gval, Gnext);
    }
}

// ---------------------------------------------------------------------------
// Main fused kernel: grid = ceil(N/96), 576 threads (18 warps).
// Warp w: row group wp = w/3 (16 rows), third = w%3 (64 centers of the tile).
// smem: A 6KB | B0 12KB | B1 12KB | G0 384B | G1 384B | bx 384B | red 1152B | mb
// ---------------------------------------------------------------------------
constexpr int SA   = 0;
constexpr int SB0  = 6144;
constexpr int SB1  = 18432;
constexpr int SG0  = 30720;
constexpr int SG1  = 31104;
constexpr int SBX  = 31488;
constexpr int SRED = 31872;          // float[3][96]
constexpr int SMB  = 33024;          // mbF0 @+0, mbF1 @+8
constexpr int STOT = 33040;

__global__ void __launch_bounds__(576, 3)
krr_main(const float* __restrict__ x, float* __restrict__ out, int N, int ntiles)
{
    __shared__ __align__(128) uint8_t smem[STOT];
    const uint32_t sbase = (uint32_t)__cvta_generic_to_shared(smem);

    const int tid   = threadIdx.x;
    const int w     = tid >> 5;
    const int lane  = tid & 31;
    const int wp    = w / 3;        // row group 0..5
    const int third = w - wp * 3;   // center third 0..2

    const uint32_t mbF[2] = {sbase + SMB, sbase + SMB + 8};

    if (tid == 0) {
        mbar_init(mbF[0], 1);
        mbar_init(mbF[1], 1);
    }
    asm volatile("fence.proxy.async.shared::cta;" ::: "memory");
    __syncthreads();

    if (tid == 0) {
        mbar_expect_tx(mbF[0], NB * ROWB + GPT * 4);
        bulk_g2s(sbase + SB0, g_cI, NB * ROWB, mbF[0]);
        bulk_g2s(sbase + SG0, g_G2, GPT * 4, mbF[0]);
        if (ntiles > 1) {
            mbar_expect_tx(mbF[1], NB * ROWB + GPT * 4);
            bulk_g2s(sbase + SB1, g_cI + (size_t)NB * ROWB, NB * ROWB, mbF[1]);
            bulk_g2s(sbase + SG1, g_G2 + GPT, GPT * 4, mbF[1]);
        }
    }

    // ---- convert this CTA's 96 x-rows into the swizzled f16 A image -------
    if (tid < 192) {
        int r  = tid >> 1;
        int hh = tid & 1;
        int gr = blockIdx.x * RC + r;
        if (gr > N - 1) gr = N - 1;

        float v[16];
        const float4* xp = reinterpret_cast<const float4*>(x + (size_t)gr * D + hh * 16);
        #pragma unroll
        for (int q = 0; q < 4; q++) {
            float4 t = xp[q];
            v[4 * q] = t.x; v[4 * q + 1] = t.y; v[4 * q + 2] = t.z; v[4 * q + 3] = t.w;
        }
        float s = 0.f;
        #pragma unroll
        for (int k = 0; k < 16; k++) s = fmaf(v[k], v[k], s);
        s += __shfl_xor_sync(0xffffffffu, s, 1);

        uint32_t wd[8];
        #pragma unroll
        for (int k = 0; k < 8; k++) wd[k] = pack_hf2(v[2 * k], v[2 * k + 1]);

        const uint32_t key = ((uint32_t)r >> 1) & 3;
        uint8_t* abase = smem + SA + r * ROWB;
        #pragma unroll
        for (int cch = 0; cch < 2; cch++) {
            uint32_t lch = (uint32_t)hh * 2 + cch;
            uint4 u = make_uint4(wd[4 * cch], wd[4 * cch + 1], wd[4 * cch + 2], wd[4 * cch + 3]);
            *reinterpret_cast<uint4*>(abase + ((lch ^ key) << 4)) = u;
        }
        if (hh == 0)
            *reinterpret_cast<float*>(smem + SBX + r * 4) = -0.5f * s * LOG2E;
    }
    __syncthreads();

    // ---- A fragments (once per warp) ----
    const uint32_t arow = (uint32_t)wp * 16 + (lane & 15);
    const uint32_t akey = (arow >> 1) & 3;
    uint32_t a[8];
    {
        uint32_t ad0 = sbase + SA + arow * ROWB + ((((uint32_t)(lane >> 4) + 0) ^ akey) << 4);
        uint32_t ad1 = sbase + SA + arow * ROWB + ((((uint32_t)(lane >> 4) + 2) ^ akey) << 4);
        ldmx4(a[0], a[1], a[2], a[3], ad0);   // k 0-15
        ldmx4(a[4], a[5], a[6], a[7], ad1);   // k 16-31
    }

    // per-row bias, packed f16x2 (global 2^10 shift lives in G')
    const float* bxsm = reinterpret_cast<const float*>(smem + SBX);
    const uint32_t bx2lo = pack_hf2(bxsm[wp * 16 + (lane >> 2)],
                                    bxsm[wp * 16 + (lane >> 2)]);
    const uint32_t bx2hi = pack_hf2(bxsm[wp * 16 + (lane >> 2) + 8],
                                    bxsm[wp * 16 + (lane >> 2) + 8]);

    // per-lane B address constant: row = lane&7, chunk = lane>>3 (swizzled)
    const uint32_t l7 = lane & 7;
    const uint32_t boff = l7 * ROWB + ((((uint32_t)lane >> 3) ^ ((l7 >> 1) & 3)) << 4)
                        + (uint32_t)third * 8 * 512;      // this third's groups
    const uint32_t goff = ((uint32_t)(lane & 3) * 24 + (uint32_t)third * 8) * 4;

    float rs_lo = 0.f, rs_hi = 0.f;

    for (int t = 0; t < ntiles; t++) {
        const int buf = t & 1;
        mbar_wait(mbF[buf], (t >> 1) & 1);

        const uint32_t bB = sbase + (buf ? SB1 : SB0) + boff;
        const uint8_t* gBp = smem + (buf ? SG1 : SG0) + goff;

        uint32_t facc01 = 0u, facc23 = 0u;

        // 8 groups, fully unrolled; G pairs via two LDS.128.
        // d23 pair: poly (fma pipe) for groups 0-5, MUFU for groups 6-7.
        uint4 q0 = *reinterpret_cast<const uint4*>(gBp);
        #pragma unroll
        for (int gg = 0; gg < 4; gg++) {
            uint32_t Gpair = (gg == 0) ? q0.x : (gg == 1) ? q0.y : (gg == 2) ? q0.z : q0.w;
            uint32_t b0, b1, b2, b3;
            ldmx4(b0, b1, b2, b3, bB + gg * 512);
            uint32_t d01 = hadd2(Gpair, bx2lo);
            uint32_t d23 = hadd2(Gpair, bx2hi);
            mma16816h(d01, d23, a[0], a[1], a[2], a[3], b0, b1);
            mma16816h(d01, d23, a[4], a[5], a[6], a[7], b2, b3);
            facc01 = hadd2(facc01, ex2_h2(d01));
            facc23 = hadd2(facc23, exp2h2_poly(d23));
        }
        uint4 q1 = *reinterpret_cast<const uint4*>(gBp + 16);
        #pragma unroll
        for (int gg = 0; gg < 4; gg++) {
            uint32_t Gpair = (gg == 0) ? q1.x : (gg == 1) ? q1.y : (gg == 2) ? q1.z : q1.w;
            uint32_t b0, b1, b2, b3;
            ldmx4(b0, b1, b2, b3, bB + (gg + 4) * 512);
            uint32_t d01 = hadd2(Gpair, bx2lo);
            uint32_t d23 = hadd2(Gpair, bx2hi);
            mma16816h(d01, d23, a[0], a[1], a[2], a[3], b0, b1);
            mma16816h(d01, d23, a[4], a[5], a[6], a[7], b2, b3);
            facc01 = hadd2(facc01, ex2_h2(d01));
            facc23 = hadd2(facc23, (gg < 2) ? exp2h2_poly(d23) : ex2_h2(d23));
        }

        rs_lo += hsum2f(facc01);   // flush 16-term f16 window to f32
        rs_hi += hsum2f(facc23);

        __syncthreads();
        if (tid == 0 && t + 2 < ntiles) {
            mbar_expect_tx(mbF[buf], NB * ROWB + GPT * 4);
            bulk_g2s(sbase + (buf ? SB1 : SB0),
                     g_cI + (size_t)(t + 2) * NB * ROWB, NB * ROWB, mbF[buf]);
            bulk_g2s(sbase + (buf ? SG1 : SG0),
                     g_G2 + (size_t)(t + 2) * GPT, GPT * 4, mbF[buf]);
        }
    }

    // ---- reduce across the 4 column-lanes, deposit per-third partials ----
    rs_lo += __shfl_xor_sync(0xffffffffu, rs_lo, 1);
    rs_lo += __shfl_xor_sync(0xffffffffu, rs_lo, 2);
    rs_hi += __shfl_xor_sync(0xffffffffu, rs_hi, 1);
    rs_hi += __shfl_xor_sync(0xffffffffu, rs_hi, 2);

    float* red = reinterpret_cast<float*>(smem + SRED);
    const int lrow = wp * 16 + (lane >> 2);
    if ((lane & 3) == 0) red[third * 96 + lrow]     = rs_lo;
    if ((lane & 3) == 1) red[third * 96 + lrow + 8] = rs_hi;
    __syncthreads();

    // ---- combine thirds, undo 2^10 shift, softplus, write ----
    if (tid < RC) {
        int r = blockIdx.x * RC + tid;
        if (r < N) {
            float s = 0.0009765625f * (red[tid] + red[96 + tid] + red[192 + tid]);
            out[r] = s + log1pf(expf(-s));
        }
    }
}

// ---------------------------------------------------------------------------
extern "C" void kernel_launch(void* const* d_in, const int* in_sizes, int n_in,
                              void* d_out, int out_size) {
    const float* x    = (const float*)d_in[0];  // (N, 32)
    const float* c    = (const float*)d_in[1];  // (M, 32)
    const float* beta = (const float*)d_in[2];  // (M,)
    float* out = (float*)d_out;                 // (N,)

    const int M = in_sizes[2];
    const int N = out_size;

    int nct = (M + NB - 1) / NB;
    if (nct > MAXCT) nct = MAXCT;
    const int mpad = nct * NB;

    prep_c<<<(mpad * 2 + 255) / 256, 256>>>(c, beta, M, mpad);

    const int grid = (N + RC - 1) / RC;
    krr_main<<<grid, 576>>>(x, out, N, nct);
}

// round 16
// speedup vs baseline: 1.1512x; 1.0107x over previous
#include <cuda_runtime.h>
#include <cuda_fp16.h>
#include <cstdint>

// ---------------------------------------------------------------------------
// softplus( exp(-0.5*||x_i - c_j||^2) @ beta ),  N=40000, M=4000, D=32.
//
// R15 == R14 with ONE change: __launch_bounds__(576, 2) instead of (576, 3).
// R14 post-mortem: regs=32 (forced by 3 CTAs/SM) starved cross-group ILP --
// the fma-pipe exp2 poly chains ran serially, wall 53.5us with every pipe
// <= 40% busy. (576,2) allows 56 regs so the 8 unrolled groups can overlap.
// Pipe floors at f=0.375 poly offload: MUFU ~24us, fma ~24us, issue ~26us.
//
//   poly path (per f16x2 pair, fma pipe):
//     v = max(v, -15); y = v + 1536 (RN-to-int); f = v - (y - 1536)
//     p = deg-2 Horner(f); s_bits = (y_bits - 0x65F165F1) << 10;  p * s
//   MUFU path: ex2.approx.f16x2 (measured rt16).
// Structure (576 thr, 6 row-groups x 3 center-thirds, NB=192, f16-accum MMA
// with G+bx+10 seeds, cp.async.bulk double buffering, in-kernel A image)
// unchanged from R10/R14.
// ---------------------------------------------------------------------------

#define LOG2E 1.4426950408889634f

constexpr int D     = 32;
constexpr int RC    = 96;        // rows per CTA
constexpr int NB    = 192;       // centers per tile
constexpr int MAXCT = 43;        // max center tiles (M <= 8256)
constexpr int MAXM  = MAXCT * NB;
constexpr int ROWB  = 64;        // bytes per f16 image row (32 f16)
constexpr int GPT   = NB / 2;    // G pairs per tile = 96

__device__ __align__(128) uint8_t g_cI[(size_t)MAXM * ROWB];  // f16(c*log2e), swizzled
__device__ uint32_t g_G2[MAXCT * GPT];  // f16x2 (G'_{2p}, G'_{2p+1}), permuted layout

// pack two f32 into f16x2: lo -> bits[0:16], hi -> bits[16:32]
__device__ __forceinline__ uint32_t pack_hf2(float lo, float hi) {
    uint32_t h;
    asm("cvt.rn.f16x2.f32 %0, %1, %2;" : "=r"(h) : "f"(hi), "f"(lo));
    return h;
}

// ---- packed f16 math -------------------------------------------------------
__device__ __forceinline__ uint32_t ex2_h2(uint32_t h) {
    uint32_t r;
    asm("ex2.approx.f16x2 %0, %1;" : "=r"(r) : "r"(h));
    return r;
}
__device__ __forceinline__ uint32_t hadd2(uint32_t a, uint32_t b) {
    uint32_t r;
    asm("add.rn.f16x2 %0, %1, %2;" : "=r"(r) : "r"(a), "r"(b));
    return r;
}
__device__ __forceinline__ uint32_t hsub2(uint32_t a, uint32_t b) {
    uint32_t r;
    asm("sub.rn.f16x2 %0, %1, %2;" : "=r"(r) : "r"(a), "r"(b));
    return r;
}
__device__ __forceinline__ uint32_t hmul2(uint32_t a, uint32_t b) {
    uint32_t r;
    asm("mul.rn.f16x2 %0, %1, %2;" : "=r"(r) : "r"(a), "r"(b));
    return r;
}
__device__ __forceinline__ uint32_t hfma2(uint32_t a, uint32_t b, uint32_t c) {
    uint32_t r;
    asm("fma.rn.f16x2 %0, %1, %2, %3;" : "=r"(r) : "r"(a), "r"(b), "r"(c));
    return r;
}
__device__ __forceinline__ uint32_t hmax2(uint32_t a, uint32_t b) {
    uint32_t r;
    asm("max.f16x2 %0, %1, %2;" : "=r"(r) : "r"(a), "r"(b));
    return r;
}
__device__ __forceinline__ float hsum2f(uint32_t h) {
    __half2 v = *reinterpret_cast<__half2*>(&h);
    float2 f = __half22float2(v);
    return f.x + f.y;
}

// packed exp2 on the fma pipe.  f16 constants:
//  -15 = 0xCB80, 1536 = 0x6600, -1536 = 0xE600
//  c2 = 0.24023 -> 0x33B0, c1 = 0.70355 -> 0x39A1, c0 = 0.99902 -> 0x3BFE
__device__ __forceinline__ uint32_t exp2h2_poly(uint32_t v) {
    v = hmax2(v, 0xCB80CB80u);            // clamp at -15 (=> s = 0 exactly)
    uint32_t y = hadd2(v, 0x66006600u);   // RN to int via magic 1536
    uint32_t z = hadd2(y, 0xE600E600u);   // z = k (exact)
    uint32_t f = hsub2(v, z);             // f in [-0.5, 0.5]
    uint32_t p = hfma2(f, 0x33B033B0u, 0x39A139A1u);
    p = hfma2(f, p, 0x3BFE3BFEu);
    uint32_t s = (y - 0x65F165F1u) << 10; // per-lane 2^k bits (k+15 in [0,26])
    return hmul2(p, s);
}

// ---- async copy / mbarrier -------------------------------------------------
__device__ __forceinline__ void mbar_init(uint32_t mb, int count) {
    asm volatile("mbarrier.init.shared.b64 [%0], %1;" :: "r"(mb), "r"(count) : "memory");
}
__device__ __forceinline__ void mbar_expect_tx(uint32_t mb, uint32_t bytes) {
    asm volatile("mbarrier.arrive.expect_tx.shared.b64 _, [%0], %1;"
                 :: "r"(mb), "r"(bytes) : "memory");
}
__device__ __forceinline__ void bulk_g2s(uint32_t sdst, const void* gsrc,
                                         uint32_t bytes, uint32_t mb) {
    asm volatile(
        "cp.async.bulk.shared::cta.global.mbarrier::complete_tx::bytes "
        "[%0], [%1], %2, [%3];"
        :: "r"(sdst), "l"(gsrc), "r"(bytes), "r"(mb) : "memory");
}
__device__ __forceinline__ void mbar_wait(uint32_t mb, uint32_t parity) {
    uint32_t done;
    asm volatile(
        "{\n\t.reg .pred p;\n\t"
        "mbarrier.try_wait.parity.acquire.cta.shared::cta.b64 p, [%1], %2;\n\t"
        "selp.b32 %0, 1, 0, p;\n\t}"
        : "=r"(done) : "r"(mb), "r"(parity) : "memory");
    if (!done) {
        asm volatile(
            "{\n\t.reg .pred P1;\n\t"
            "WL_%=:\n\t"
            "mbarrier.try_wait.parity.acquire.cta.shared::cta.b64 P1, [%0], %1, 0x989680;\n\t"
            "@P1 bra.uni WD_%=;\n\t"
            "bra.uni WL_%=;\n\t"
            "WD_%=:\n\t}"
            :: "r"(mb), "r"(parity) : "memory");
    }
}

// ---- warp MMA primitives ---------------------------------------------------
__device__ __forceinline__ void ldmx4(uint32_t& r0, uint32_t& r1,
                                      uint32_t& r2, uint32_t& r3, uint32_t addr) {
    asm volatile("ldmatrix.sync.aligned.m8n8.x4.shared.b16 {%0,%1,%2,%3}, [%4];"
                 : "=r"(r0), "=r"(r1), "=r"(r2), "=r"(r3) : "r"(addr));
}

__device__ __forceinline__ void mma16816h(uint32_t& d01, uint32_t& d23,
                                          uint32_t a0, uint32_t a1, uint32_t a2, uint32_t a3,
                                          uint32_t b0, uint32_t b1) {
    asm volatile(
        "mma.sync.aligned.m16n8k16.row.col.f16.f16.f16.f16 "
        "{%0,%1}, {%2,%3,%4,%5}, {%6,%7}, {%0,%1};"
        : "+r"(d01), "+r"(d23)
        : "r"(a0), "r"(a1), "r"(a2), "r"(a3), "r"(b0), "r"(b1));
}

// ---------------------------------------------------------------------------
// prep_c: one thread per HALF center row. Writes the 64B f16 image row
// (c*log2e, chunk swizzle phys = logical ^ ((j>>1)&3)) and, for pair leaders,
// G' pair f16x2 in the permuted layout [tile][colpair 0..3][group 0..23].
// G' = -0.5||c||^2*log2e + log2(beta) + 10; padded rows: zero image, G' = -30000.
// ---------------------------------------------------------------------------
__global__ void prep_c(const float* __restrict__ c,
                       const float* __restrict__ beta, int M, int mpad) {
    int idx  = blockIdx.x * blockDim.x + threadIdx.x;
    int j    = idx >> 1;
    int half = idx & 1;
    int lane = idx & 31;
    if (j >= mpad) return;

    float v[16];
    if (j < M) {
        const float4* cp = reinterpret_cast<const float4*>(c + (size_t)j * D + half * 16);
        #pragma unroll
        for (int q = 0; q < 4; q++) {
            float4 t = cp[q];
            v[4 * q] = t.x; v[4 * q + 1] = t.y; v[4 * q + 2] = t.z; v[4 * q + 3] = t.w;
        }
    } else {
        #pragma unroll
        for (int k = 0; k < 16; k++) v[k] = 0.f;
    }
    float s = 0.f;
    #pragma unroll
    for (int k = 0; k < 16; k++) {
        s = fmaf(v[k], v[k], s);
        v[k] *= LOG2E;
    }
    s += __shfl_xor_sync(0xffffffffu, s, 1);   // full ||c||^2

    uint32_t wd[8];
    #pragma unroll
    for (int k = 0; k < 8; k++) wd[k] = pack_hf2(v[2 * k], v[2 * k + 1]);

    const uint32_t key = ((uint32_t)j >> 1) & 3;
    uint8_t* base = g_cI + (size_t)j * ROWB;
    #pragma unroll
    for (int cch = 0; cch < 2; cch++) {
        uint32_t lch = (uint32_t)half * 2 + cch;
        uint4 u = make_uint4(wd[4 * cch], wd[4 * cch + 1], wd[4 * cch + 2], wd[4 * cch + 3]);
        *reinterpret_cast<uint4*>(base + ((lch ^ key) << 4)) = u;
    }

    float Gval = (j < M) ? (fmaf(-0.5f * LOG2E, s, log2f(beta[j])) + 10.0f)
                         : -30000.0f;
    float Gnext = __shfl_down_sync(0xffffffffu, Gval, 2);   // G'(j+1)
    if ((lane & 3) == 0) {      // j even, half 0
        int p  = j >> 1;        // global pair index
        int T  = p / GPT;
        int pi = p - T * GPT;   // 0..95
        g_G2[T * GPT + (pi & 3) * 24 + (pi >> 2)] = pack_hf2(Gval, Gnext);
    }
}

// ---------------------------------------------------------------------------
// Main fused kernel: grid = ceil(N/96), 576 threads (18 warps).
// Warp w: row group wp = w/3 (16 rows), third = w%3 (64 centers of the tile).
// smem: A 6KB | B0 12KB | B1 12KB | G0 384B | G1 384B | bx 384B | red 1152B | mb
// ---------------------------------------------------------------------------
constexpr int SA   = 0;
constexpr int SB0  = 6144;
constexpr int SB1  = 18432;
constexpr int SG0  = 30720;
constexpr int SG1  = 31104;
constexpr int SBX  = 31488;
constexpr int SRED = 31872;          // float[3][96]
constexpr int SMB  = 33024;          // mbF0 @+0, mbF1 @+8
constexpr int STOT = 33040;

__global__ void __launch_bounds__(576, 2)
krr_main(const float* __restrict__ x, float* __restrict__ out, int N, int ntiles)
{
    __shared__ __align__(128) uint8_t smem[STOT];
    const uint32_t sbase = (uint32_t)__cvta_generic_to_shared(smem);

    const int tid   = threadIdx.x;
    const int w     = tid >> 5;
    const int lane  = tid & 31;
    const int wp    = w / 3;        // row group 0..5
    const int third = w - wp * 3;   // center third 0..2

    const uint32_t mbF[2] = {sbase + SMB, sbase + SMB + 8};

    if (tid == 0) {
        mbar_init(mbF[0], 1);
        mbar_init(mbF[1], 1);
    }
    asm volatile("fence.proxy.async.shared::cta;" ::: "memory");
    __syncthreads();

    if (tid == 0) {
        mbar_expect_tx(mbF[0], NB * ROWB + GPT * 4);
        bulk_g2s(sbase + SB0, g_cI, NB * ROWB, mbF[0]);
        bulk_g2s(sbase + SG0, g_G2, GPT * 4, mbF[0]);
        if (ntiles > 1) {
            mbar_expect_tx(mbF[1], NB * ROWB + GPT * 4);
            bulk_g2s(sbase + SB1, g_cI + (size_t)NB * ROWB, NB * ROWB, mbF[1]);
            bulk_g2s(sbase + SG1, g_G2 + GPT, GPT * 4, mbF[1]);
        }
    }

    // ---- convert this CTA's 96 x-rows into the swizzled f16 A image -------
    if (tid < 192) {
        int r  = tid >> 1;
        int hh = tid & 1;
        int gr = blockIdx.x * RC + r;
        if (gr > N - 1) gr = N - 1;

        float v[16];
        const float4* xp = reinterpret_cast<const float4*>(x + (size_t)gr * D + hh * 16);
        #pragma unroll
        for (int q = 0; q < 4; q++) {
            float4 t = xp[q];
            v[4 * q] = t.x; v[4 * q + 1] = t.y; v[4 * q + 2] = t.z; v[4 * q + 3] = t.w;
        }
        float s = 0.f;
        #pragma unroll
        for (int k = 0; k < 16; k++) s = fmaf(v[k], v[k], s);
        s += __shfl_xor_sync(0xffffffffu, s, 1);

        uint32_t wd[8];
        #pragma unroll
        for (int k = 0; k < 8; k++) wd[k] = pack_hf2(v[2 * k], v[2 * k + 1]);

        const uint32_t key = ((uint32_t)r >> 1) & 3;
        uint8_t* abase = smem + SA + r * ROWB;
        #pragma unroll
        for (int cch = 0; cch < 2; cch++) {
            uint32_t lch = (uint32_t)hh * 2 + cch;
            uint4 u = make_uint4(wd[4 * cch], wd[4 * cch + 1], wd[4 * cch + 2], wd[4 * cch + 3]);
            *reinterpret_cast<uint4*>(abase + ((lch ^ key) << 4)) = u;
        }
        if (hh == 0)
            *reinterpret_cast<float*>(smem + SBX + r * 4) = -0.5f * s * LOG2E;
    }
    __syncthreads();

    // ---- A fragments (once per warp) ----
    const uint32_t arow = (uint32_t)wp * 16 + (lane & 15);
    const uint32_t akey = (arow >> 1) & 3;
    uint32_t a[8];
    {
        uint32_t ad0 = sbase + SA + arow * ROWB + ((((uint32_t)(lane >> 4) + 0) ^ akey) << 4);
        uint32_t ad1 = sbase + SA + arow * ROWB + ((((uint32_t)(lane >> 4) + 2) ^ akey) << 4);
        ldmx4(a[0], a[1], a[2], a[3], ad0);   // k 0-15
        ldmx4(a[4], a[5], a[6], a[7], ad1);   // k 16-31
    }

    // per-row bias, packed f16x2 (global 2^10 shift lives in G')
    const float* bxsm = reinterpret_cast<const float*>(smem + SBX);
    const uint32_t bx2lo = pack_hf2(bxsm[wp * 16 + (lane >> 2)],
                                    bxsm[wp * 16 + (lane >> 2)]);
    const uint32_t bx2hi = pack_hf2(bxsm[wp * 16 + (lane >> 2) + 8],
                                    bxsm[wp * 16 + (lane >> 2) + 8]);

    // per-lane B address constant: row = lane&7, chunk = lane>>3 (swizzled)
    const uint32_t l7 = lane & 7;
    const uint32_t boff = l7 * ROWB + ((((uint32_t)lane >> 3) ^ ((l7 >> 1) & 3)) << 4)
                        + (uint32_t)third * 8 * 512;      // this third's groups
    const uint32_t goff = ((uint32_t)(lane & 3) * 24 + (uint32_t)third * 8) * 4;

    float rs_lo = 0.f, rs_hi = 0.f;

    for (int t = 0; t < ntiles; t++) {
        const int buf = t & 1;
        mbar_wait(mbF[buf], (t >> 1) & 1);

        const uint32_t bB = sbase + (buf ? SB1 : SB0) + boff;
        const uint8_t* gBp = smem + (buf ? SG1 : SG0) + goff;

        uint32_t facc01 = 0u, facc23 = 0u;

        // 8 groups, fully unrolled; G pairs via two LDS.128.
        // d23 pair: poly (fma pipe) for groups 0-5, MUFU for groups 6-7.
        uint4 q0 = *reinterpret_cast<const uint4*>(gBp);
        #pragma unroll
        for (int gg = 0; gg < 4; gg++) {
            uint32_t Gpair = (gg == 0) ? q0.x : (gg == 1) ? q0.y : (gg == 2) ? q0.z : q0.w;
            uint32_t b0, b1, b2, b3;
            ldmx4(b0, b1, b2, b3, bB + gg * 512);
            uint32_t d01 = hadd2(Gpair, bx2lo);
            uint32_t d23 = hadd2(Gpair, bx2hi);
            mma16816h(d01, d23, a[0], a[1], a[2], a[3], b0, b1);
            mma16816h(d01, d23, a[4], a[5], a[6], a[7], b2, b3);
            facc01 = hadd2(facc01, ex2_h2(d01));
            facc23 = hadd2(facc23, exp2h2_poly(d23));
        }
        uint4 q1 = *reinterpret_cast<const uint4*>(gBp + 16);
        #pragma unroll
        for (int gg = 0; gg < 4; gg++) {
            uint32_t Gpair = (gg == 0) ? q1.x : (gg == 1) ? q1.y : (gg == 2) ? q1.z : q1.w;
            uint32_t b0, b1, b2, b3;
            ldmx4(b0, b1, b2, b3, bB + (gg + 4) * 512);
            uint32_t d01 = hadd2(Gpair, bx2lo);
            uint32_t d23 = hadd2(Gpair, bx2hi);
            mma16816h(d01, d23, a[0], a[1], a[2], a[3], b0, b1);
            mma16816h(d01, d23, a[4], a[5], a[6], a[7], b2, b3);
            facc01 = hadd2(facc01, ex2_h2(d01));
            facc23 = hadd2(facc23, (gg < 2) ? exp2h2_poly(d23) : ex2_h2(d23));
        }

        rs_lo += hsum2f(facc01);   // flush 16-term f16 window to f32
        rs_hi += hsum2f(facc23);

        __syncthreads();
        if (tid == 0 && t + 2 < ntiles) {
            mbar_expect_tx(mbF[buf], NB * ROWB + GPT * 4);
            bulk_g2s(sbase + (buf ? SB1 : SB0),
                     g_cI + (size_t)(t + 2) * NB * ROWB, NB * ROWB, mbF[buf]);
            bulk_g2s(sbase + (buf ? SG1 : SG0),
                     g_G2 + (size_t)(t + 2) * GPT, GPT * 4, mbF[buf]);
        }
    }

    // ---- reduce across the 4 column-lanes, deposit per-third partials ----
    rs_lo += __shfl_xor_sync(0xffffffffu, rs_lo, 1);
    rs_lo += __shfl_xor_sync(0xffffffffu, rs_lo, 2);
    rs_hi += __shfl_xor_sync(0xffffffffu, rs_hi, 1);
    rs_hi += __shfl_xor_sync(0xffffffffu, rs_hi, 2);

    float* red = reinterpret_cast<float*>(smem + SRED);
    const int lrow = wp * 16 + (lane >> 2);
    if ((lane & 3) == 0) red[third * 96 + lrow]     = rs_lo;
    if ((lane & 3) == 1) red[third * 96 + lrow + 8] = rs_hi;
    __syncthreads();

    // ---- combine thirds, undo 2^10 shift, softplus, write ----
    if (tid < RC) {
        int r = blockIdx.x * RC + tid;
        if (r < N) {
            float s = 0.0009765625f * (red[tid] + red[96 + tid] + red[192 + tid]);
            out[r] = s + log1pf(expf(-s));
        }
    }
}

// ---------------------------------------------------------------------------
extern "C" void kernel_launch(void* const* d_in, const int* in_sizes, int n_in,
                              void* d_out, int out_size) {
    const float* x    = (const float*)d_in[0];  // (N, 32)
    const float* c    = (const float*)d_in[1];  // (M, 32)
    const float* beta = (const float*)d_in[2];  // (M,)
    float* out = (float*)d_out;                 // (N,)

    const int M = in_sizes[2];
    const int N = out_size;

    int nct = (M + NB - 1) / NB;
    if (nct > MAXCT) nct = MAXCT;
    const int mpad = nct * NB;

    prep_c<<<(mpad * 2 + 255) / 256, 256>>>(c, beta, M, mpad);

    const int grid = (N + RC - 1) / RC;
    krr_main<<<grid, 576>>>(x, out, N, nct);
}